// round 5
// baseline (speedup 1.0000x reference)
#include <cuda_runtime.h>
#include <cuda_bf16.h>
#include <mma.h>

using namespace nvcuda;

// Problem constants
#define BB   256
#define TT   32
#define SS   2048
#define AA   64
#define PP   128
#define KFC  (SS + AA + PP)   // 2240
#define S4   (4 * SS)         // 8192

// GEMM tiling
#define BM   64
#define BN   64
#define BKT  64
#define LDT  (BKT + 8)        // 72 bf16 smem stride (144B, 16B-aligned rows)
#define LDC  (BN + 4)         // 68 float staging stride

// ---------------------------------------------------------------------------
// Scratch (static device globals; no allocation anywhere)
// ---------------------------------------------------------------------------
__device__ __nv_bfloat16 g_fc1e[(long)SS * 2 * SS];    // fc1_eff packed [hi|lo]
__device__ __nv_bfloat16 g_fc2b[(long)SS * 2 * SS];
__device__ __nv_bfloat16 g_WWb [(long)S4 * 2 * SS];
__device__ __nv_bfloat16 g_fcWb[(long)SS * 2 * KFC];
__device__ __nv_bfloat16 g_hb  [(long)BB * 2 * SS];    // carry h, packed
__device__ __nv_bfloat16 g_x1b [(long)BB * 2 * SS];
__device__ __nv_bfloat16 g_x2b [(long)BB * 2 * SS];
__device__ __nv_bfloat16 g_hsb [(long)BB * 2 * KFC];   // cat[h, act, latent], packed
__device__ float         g_cc  [(long)BB * S4];
__device__ float         g_cell[(long)BB * SS];

// ---------------------------------------------------------------------------
// Helpers
// ---------------------------------------------------------------------------
__device__ __forceinline__ void split_write(__nv_bfloat16* hi_p, __nv_bfloat16* lo_p, float v) {
    __nv_bfloat16 h = __float2bfloat16(v);
    *hi_p = h;
    *lo_p = __float2bfloat16(v - __bfloat162float(h));
}

// Pack a fp32 weight [N][K] into split-bf16 [N][2K] = [hi | lo]
__global__ void pack_weight(const float* __restrict__ src, __nv_bfloat16* __restrict__ dst,
                            int K, long total) {
    long idx = (long)blockIdx.x * 256 + threadIdx.x;
    if (idx >= total) return;
    long n = idx / K, k = idx % K;
    split_write(&dst[n * 2 * K + k], &dst[n * 2 * K + K + k], src[idx]);
}

// fc1_eff[n][k] = fc1_W[n][k] + fc1_W[n][S+k], then split
__global__ void pack_fc1eff(const float* __restrict__ fc1W, __nv_bfloat16* __restrict__ dst) {
    long idx = (long)blockIdx.x * 256 + threadIdx.x;
    long n = idx / SS, k = idx % SS;
    float v = fc1W[n * 2 * SS + k] + fc1W[n * 2 * SS + SS + k];
    split_write(&dst[n * 2 * SS + k], &dst[n * 2 * SS + SS + k], v);
}

// hs0 = cat[state, act[:,0,:], latent], split-packed
__global__ void build_hs0(const float* __restrict__ state, const float* __restrict__ acts,
                          const float* __restrict__ latent, __nv_bfloat16* __restrict__ hs) {
    long idx = (long)blockIdx.x * 256 + threadIdx.x;
    if (idx >= (long)BB * KFC) return;
    int b = (int)(idx / KFC), j = (int)(idx % KFC);
    float v;
    if (j < SS)            v = state[(long)b * SS + j];
    else if (j < SS + AA)  v = acts[(long)b * (TT * AA) + (j - SS)];
    else                   v = latent[(long)b * PP + (j - SS - AA)];
    split_write(&hs[(long)b * 2 * KFC + j], &hs[(long)b * 2 * KFC + KFC + j], v);
}

// ---------------------------------------------------------------------------
// Split-bf16 GEMM:  C[M=256, N] = relu( A[256,K] @ W[N,K]^T (+bias) )
// A, W stored packed [.,2K] bf16 as [hi|lo]; the K loop runs 3 segments:
//   (a_hi,w_hi), (a_hi,w_lo), (a_lo,w_hi)  -> ~fp32-quality result.
// EPI: 0 = fp32 store (relu)              [cc for gates]
//      1 = split-bf16 store (relu)        [x1, x2]
//      2 = bias + split-bf16 store (relu) [carry h]
//      3 = like 2, plus fp32 dual store   [init: h and cell]
// ---------------------------------------------------------------------------
#define CP16(s, g) asm volatile("cp.async.cg.shared.global [%0], [%1], 16;\n" :: "r"(s), "l"(g))

template<int EPI>
__global__ __launch_bounds__(128)
void gemm_split(const __nv_bfloat16* __restrict__ Ab,
                const __nv_bfloat16* __restrict__ Wb,
                const float* __restrict__ bias,
                void* __restrict__ Cout,
                float* __restrict__ Cdual,
                int N, int K)
{
    __shared__ alignas(16) __nv_bfloat16 sA[2][BM][LDT];
    __shared__ alignas(16) __nv_bfloat16 sW[2][BN][LDT];

    const int tid = threadIdx.x;
    const int m0 = blockIdx.y * BM;
    const int n0 = blockIdx.x * BN;
    const int lda = 2 * K;             // both packed buffers have row stride 2K
    const int nkc = K / BKT;
    const int nchunks = 3 * nkc;

    auto load_tile = [&](int buf, int c) {
        int seg   = c / nkc;
        int kbase = (c - seg * nkc) * BKT;
        int aoff  = (seg == 2) ? K : 0;
        int woff  = (seg == 1) ? K : 0;
#pragma unroll
        for (int i = 0; i < 4; ++i) {
            int f = tid + 128 * i;       // 512 x 16B per tile
            int row = f >> 3;
            int cb  = (f & 7) * 8;       // bf16 elements
            const __nv_bfloat16* ga = Ab + (long)(m0 + row) * lda + aoff + kbase + cb;
            unsigned sa = (unsigned)__cvta_generic_to_shared(&sA[buf][row][cb]);
            CP16(sa, ga);
            const __nv_bfloat16* gw = Wb + (long)(n0 + row) * lda + woff + kbase + cb;
            unsigned sw = (unsigned)__cvta_generic_to_shared(&sW[buf][row][cb]);
            CP16(sw, gw);
        }
    };

    const int w  = tid >> 5;
    const int wy = w >> 1, wx = w & 1;   // 2x2 warp grid, 32x32 per warp

    wmma::fragment<wmma::accumulator, 16, 16, 16, float> acc[2][2];
#pragma unroll
    for (int i = 0; i < 2; ++i)
#pragma unroll
        for (int j = 0; j < 2; ++j) wmma::fill_fragment(acc[i][j], 0.0f);

    load_tile(0, 0);
    asm volatile("cp.async.commit_group;\n");

    for (int c = 0; c < nchunks; ++c) {
        int cur = c & 1;
        if (c + 1 < nchunks) {
            load_tile(cur ^ 1, c + 1);
            asm volatile("cp.async.commit_group;\n");
            asm volatile("cp.async.wait_group 1;\n");
        } else {
            asm volatile("cp.async.wait_group 0;\n");
        }
        __syncthreads();
#pragma unroll
        for (int ks = 0; ks < BKT / 16; ++ks) {
            wmma::fragment<wmma::matrix_a, 16, 16, 16, __nv_bfloat16, wmma::row_major> af[2];
            wmma::fragment<wmma::matrix_b, 16, 16, 16, __nv_bfloat16, wmma::col_major> bf[2];
            wmma::load_matrix_sync(af[0], &sA[cur][wy * 32     ][ks * 16], LDT);
            wmma::load_matrix_sync(af[1], &sA[cur][wy * 32 + 16][ks * 16], LDT);
            wmma::load_matrix_sync(bf[0], &sW[cur][wx * 32     ][ks * 16], LDT);
            wmma::load_matrix_sync(bf[1], &sW[cur][wx * 32 + 16][ks * 16], LDT);
#pragma unroll
            for (int i = 0; i < 2; ++i)
#pragma unroll
                for (int j = 0; j < 2; ++j)
                    wmma::mma_sync(acc[i][j], af[i], bf[j], acc[i][j]);
        }
        __syncthreads();
    }

    // Epilogue: stage accumulators in smem (reuse sA), then coalesced writes.
    float* stage = reinterpret_cast<float*>(&sA[0][0][0]);
#pragma unroll
    for (int i = 0; i < 2; ++i)
#pragma unroll
        for (int j = 0; j < 2; ++j)
            wmma::store_matrix_sync(stage + (wy * 32 + 16 * i) * LDC + wx * 32 + 16 * j,
                                    acc[i][j], LDC, wmma::mem_row_major);
    __syncthreads();

#pragma unroll
    for (int i = 0; i < 8; ++i) {
        int f = tid + 128 * i;           // 1024 groups of 4 floats
        int row = f >> 4;
        int c4  = (f & 15) * 4;
        float4 v4 = *reinterpret_cast<float4*>(&stage[row * LDC + c4]);
        float v[4] = {v4.x, v4.y, v4.z, v4.w};
#pragma unroll
        for (int q = 0; q < 4; ++q) {
            if (EPI >= 2) v[q] += bias[n0 + c4 + q];
            v[q] = fmaxf(v[q], 0.0f);
        }
        long gm = m0 + row;
        if (EPI == 0) {
            *reinterpret_cast<float4*>((float*)Cout + gm * N + n0 + c4) =
                make_float4(v[0], v[1], v[2], v[3]);
        } else {
            __nv_bfloat16* cp = (__nv_bfloat16*)Cout + gm * (2L * N);
            __nv_bfloat16 h[4]; float lo[4];
#pragma unroll
            for (int q = 0; q < 4; ++q) {
                h[q]  = __float2bfloat16(v[q]);
                lo[q] = v[q] - __bfloat162float(h[q]);
            }
            __nv_bfloat162 hh0; hh0.x = h[0]; hh0.y = h[1];
            __nv_bfloat162 hh1; hh1.x = h[2]; hh1.y = h[3];
            reinterpret_cast<__nv_bfloat162*>(cp + n0 + c4)[0] = hh0;
            reinterpret_cast<__nv_bfloat162*>(cp + n0 + c4)[1] = hh1;
            __nv_bfloat162 ll0; ll0.x = __float2bfloat16(lo[0]); ll0.y = __float2bfloat16(lo[1]);
            __nv_bfloat162 ll1; ll1.x = __float2bfloat16(lo[2]); ll1.y = __float2bfloat16(lo[3]);
            reinterpret_cast<__nv_bfloat162*>(cp + N + n0 + c4)[0] = ll0;
            reinterpret_cast<__nv_bfloat162*>(cp + N + n0 + c4)[1] = ll1;
            if (EPI == 3) {
                *reinterpret_cast<float4*>(Cdual + gm * N + n0 + c4) =
                    make_float4(v[0], v[1], v[2], v[3]);
            }
        }
    }
}

// ---------------------------------------------------------------------------
// LSTM gates + reward + hs concat, fused. One block per batch row.
// ---------------------------------------------------------------------------
__global__ __launch_bounds__(256)
void gates_kernel(const float* __restrict__ cc, float* __restrict__ cell,
                  const float* __restrict__ rW, const float* __restrict__ rb,
                  const float* __restrict__ acts, const float* __restrict__ latent,
                  int t, float* __restrict__ preds, float* __restrict__ rewards,
                  __nv_bfloat16* __restrict__ hs)
{
    const int b = blockIdx.x, tid = threadIdx.x;
    const float* ccb = cc + (long)b * S4;
    float* cb  = cell + (long)b * SS;
    float* pr  = preds + ((long)t * BB + b) * SS;
    __nv_bfloat16* hsb = hs + (long)b * (2 * KFC);

    float rsum = 0.f;
#pragma unroll
    for (int i = 0; i < 8; ++i) {
        int s = tid + i * 256;
        float ci = ccb[s];
        float cf = ccb[SS + s];
        float co = ccb[2 * SS + s];
        float cg = ccb[3 * SS + s];
        float ig = 1.f / (1.f + expf(-ci));
        float fg = 1.f / (1.f + expf(-cf));
        float og = 1.f / (1.f + expf(-co));
        float gg = tanhf(cg);
        float cn = fg * cb[s] + ig * gg;
        cb[s] = cn;
        float h = og * tanhf(cn);
        pr[s] = h;
        split_write(&hsb[s], &hsb[KFC + s], h);
        rsum += h * rW[s];
    }

    __shared__ float red[256];
    red[tid] = rsum;
    __syncthreads();
    for (int s2 = 128; s2 > 0; s2 >>= 1) {
        if (tid < s2) red[tid] += red[tid + s2];
        __syncthreads();
    }
    if (tid == 0) rewards[(long)t * BB + b] = red[0] + rb[0];

    // hs tail: act_t then latent
    if (tid < AA) {
        float v = acts[(long)b * (TT * AA) + t * AA + tid];
        split_write(&hsb[SS + tid], &hsb[KFC + SS + tid], v);
    } else if (tid < AA + PP) {
        int j = tid - AA;
        float v = latent[(long)b * PP + j];
        split_write(&hsb[SS + AA + j], &hsb[KFC + SS + AA + j], v);
    }
}

// ---------------------------------------------------------------------------
// Launch
// ---------------------------------------------------------------------------
extern "C" void kernel_launch(void* const* d_in, const int* /*in_sizes*/, int /*n_in*/,
                              void* d_out, int /*out_size*/) {
    const float* state  = (const float*)d_in[0];
    const float* acts   = (const float*)d_in[1];
    const float* latent = (const float*)d_in[2];
    const float* fcW    = (const float*)d_in[3];
    const float* fcb    = (const float*)d_in[4];
    const float* fc1W   = (const float*)d_in[5];
    const float* fc2W   = (const float*)d_in[6];
    const float* WW     = (const float*)d_in[7];
    const float* rW     = (const float*)d_in[8];
    const float* rb     = (const float*)d_in[9];

    float* preds   = (float*)d_out;
    float* rewards = preds + (long)TT * BB * SS;

    __nv_bfloat16 *fc1e, *fc2b, *WWb, *fcWb, *hb, *x1b, *x2b, *hsb;
    float *cc, *cell;
    cudaGetSymbolAddress((void**)&fc1e, g_fc1e);
    cudaGetSymbolAddress((void**)&fc2b, g_fc2b);
    cudaGetSymbolAddress((void**)&WWb,  g_WWb);
    cudaGetSymbolAddress((void**)&fcWb, g_fcWb);
    cudaGetSymbolAddress((void**)&hb,   g_hb);
    cudaGetSymbolAddress((void**)&x1b,  g_x1b);
    cudaGetSymbolAddress((void**)&x2b,  g_x2b);
    cudaGetSymbolAddress((void**)&hsb,  g_hsb);
    cudaGetSymbolAddress((void**)&cc,   g_cc);
    cudaGetSymbolAddress((void**)&cell, g_cell);

    // Weight packing (runs on every replay; ~1% of total time)
    pack_fc1eff<<<(unsigned)(((long)SS * SS) / 256), 256>>>(fc1W, fc1e);
    pack_weight<<<(unsigned)(((long)SS * SS) / 256), 256>>>(fc2W, fc2b, SS,  (long)SS * SS);
    pack_weight<<<(unsigned)(((long)S4 * SS) / 256), 256>>>(WW,   WWb,  SS,  (long)S4 * SS);
    pack_weight<<<(unsigned)(((long)SS * KFC) / 256), 256>>>(fcW, fcWb, KFC, (long)SS * KFC);
    build_hs0<<<(unsigned)(((long)BB * KFC) / 256), 256>>>(state, acts, latent, hsb);

    dim3 blk(128);
    dim3 g2048(SS / BN, BB / BM);   // (32, 4)
    dim3 g8192(S4 / BN, BB / BM);   // (128, 4)

    // hidden = cell = relu(fc(hs0)): one GEMM, dual store
    gemm_split<3><<<g2048, blk>>>(hsb, fcWb, fcb, hb, cell, SS, KFC);

    for (int t = 0; t < TT; ++t) {
        gemm_split<1><<<g2048, blk>>>(hb,  fc1e, nullptr, x1b, nullptr, SS, SS);
        gemm_split<1><<<g2048, blk>>>(x1b, fc2b, nullptr, x2b, nullptr, SS, SS);
        gemm_split<0><<<g8192, blk>>>(x2b, WWb,  nullptr, cc,  nullptr, S4, SS);
        gates_kernel<<<BB, 256>>>(cc, cell, rW, rb, acts, latent, t, preds, rewards, hsb);
        if (t + 1 < TT)
            gemm_split<2><<<g2048, blk>>>(hsb, fcWb, fcb, hb, nullptr, SS, KFC);
    }
}

// round 6
// speedup vs baseline: 1.4218x; 1.4218x over previous
#include <cuda_runtime.h>
#include <cuda_bf16.h>
#include <mma.h>

using namespace nvcuda;

// Problem constants
#define BB   256
#define TT   32
#define SS   2048
#define AA   64
#define PP   128
#define KFC  (SS + AA + PP)   // 2240
#define S4   (4 * SS)         // 8192

#define BKT  64
#define LDT  (BKT + 8)        // 72 bf16 smem stride

// ---------------------------------------------------------------------------
// Scratch (static device globals; no allocation anywhere)
// ---------------------------------------------------------------------------
__device__ __nv_bfloat16 g_fc1e[(long)SS * 2 * SS];    // fc1_eff packed [hi|lo]
__device__ __nv_bfloat16 g_fc2b[(long)SS * 2 * SS];
__device__ __nv_bfloat16 g_WWb [(long)S4 * 2 * SS];
__device__ __nv_bfloat16 g_fcWb[(long)SS * 2 * KFC];
__device__ __nv_bfloat16 g_hb  [(long)BB * 2 * SS];    // carry h, packed
__device__ __nv_bfloat16 g_x1b [(long)BB * 2 * SS];
__device__ __nv_bfloat16 g_x2b [(long)BB * 2 * SS];
__device__ __nv_bfloat16 g_hsb [(long)BB * 2 * KFC];   // cat[h, act, latent], packed
__device__ float         g_cc  [(long)BB * S4];
__device__ float         g_cell[(long)BB * SS];

// ---------------------------------------------------------------------------
// Helpers
// ---------------------------------------------------------------------------
__device__ __forceinline__ void split_write(__nv_bfloat16* hi_p, __nv_bfloat16* lo_p, float v) {
    __nv_bfloat16 h = __float2bfloat16(v);
    *hi_p = h;
    *lo_p = __float2bfloat16(v - __bfloat162float(h));
}

__global__ void pack_weight(const float* __restrict__ src, __nv_bfloat16* __restrict__ dst,
                            int K, long total) {
    long idx = (long)blockIdx.x * 256 + threadIdx.x;
    if (idx >= total) return;
    long n = idx / K, k = idx % K;
    split_write(&dst[n * 2 * K + k], &dst[n * 2 * K + K + k], src[idx]);
}

__global__ void pack_fc1eff(const float* __restrict__ fc1W, __nv_bfloat16* __restrict__ dst) {
    long idx = (long)blockIdx.x * 256 + threadIdx.x;
    long n = idx / SS, k = idx % SS;
    float v = fc1W[n * 2 * SS + k] + fc1W[n * 2 * SS + SS + k];
    split_write(&dst[n * 2 * SS + k], &dst[n * 2 * SS + SS + k], v);
}

__global__ void build_hs0(const float* __restrict__ state, const float* __restrict__ acts,
                          const float* __restrict__ latent, __nv_bfloat16* __restrict__ hs) {
    long idx = (long)blockIdx.x * 256 + threadIdx.x;
    if (idx >= (long)BB * KFC) return;
    int b = (int)(idx / KFC), j = (int)(idx % KFC);
    float v;
    if (j < SS)            v = state[(long)b * SS + j];
    else if (j < SS + AA)  v = acts[(long)b * (TT * AA) + (j - SS)];
    else                   v = latent[(long)b * PP + (j - SS - AA)];
    split_write(&hs[(long)b * 2 * KFC + j], &hs[(long)b * 2 * KFC + KFC + j], v);
}

// ---------------------------------------------------------------------------
// Split-bf16 GEMM with fused segment loading:
//   C[M=256, N] = relu( A @ W^T (+bias) ),  A,W packed [.,2K] bf16 [hi|lo].
// Per 64-wide k-chunk we load 4 tiles {A_hi, A_lo, W_hi, W_lo} once and do
// acc += Ah*Wh + Ah*Wl + Al*Wh  (Ozaki 3-term, ~fp32 quality).
// EPI: 0 fp32 store; 1 split-bf16 store; 2 +bias split-bf16; 3 = 2 + fp32 dual.
// ---------------------------------------------------------------------------
#define CP16(s, g) asm volatile("cp.async.cg.shared.global [%0], [%1], 16;\n" :: "r"(s), "l"(g))

template<int BMp, int BNp, int WM, int WN, int THREADS, int STAGES, int EPI>
__global__ __launch_bounds__(THREADS, 1)
void gemm3(const __nv_bfloat16* __restrict__ Ab,
           const __nv_bfloat16* __restrict__ Wb,
           const float* __restrict__ bias,
           void* __restrict__ Cout,
           float* __restrict__ Cdual,
           int N, int K)
{
    extern __shared__ __align__(16) __nv_bfloat16 smem[];
    constexpr int TA = BMp * LDT;
    constexpr int TW = BNp * LDT;
    constexpr int STG = 2 * TA + 2 * TW;   // elements per stage

    const int tid = threadIdx.x;
    const int m0 = blockIdx.y * BMp;
    const int n0 = blockIdx.x * BNp;
    const int lda = 2 * K;
    const int nchunks = K / BKT;

    auto load_stage = [&](int buf, int c) {
        const int kb = c * BKT;
        __nv_bfloat16* sAhi = smem + buf * STG;
        __nv_bfloat16* sAlo = sAhi + TA;
        __nv_bfloat16* sWhi = sAlo + TA;
        __nv_bfloat16* sWlo = sWhi + TW;
#pragma unroll
        for (int i = 0; i < BMp * 8 / THREADS; ++i) {
            int f = tid + i * THREADS;
            int r = f >> 3, cb = (f & 7) * 8;
            const __nv_bfloat16* g = Ab + (long)(m0 + r) * lda + kb + cb;
            CP16((unsigned)__cvta_generic_to_shared(sAhi + r * LDT + cb), g);
            CP16((unsigned)__cvta_generic_to_shared(sAlo + r * LDT + cb), g + K);
        }
#pragma unroll
        for (int i = 0; i < BNp * 8 / THREADS; ++i) {
            int f = tid + i * THREADS;
            int r = f >> 3, cb = (f & 7) * 8;
            const __nv_bfloat16* g = Wb + (long)(n0 + r) * lda + kb + cb;
            CP16((unsigned)__cvta_generic_to_shared(sWhi + r * LDT + cb), g);
            CP16((unsigned)__cvta_generic_to_shared(sWlo + r * LDT + cb), g + K);
        }
        asm volatile("cp.async.commit_group;\n");
    };

    constexpr int WGX = BNp / WN;
    constexpr int MI = WM / 16, NI = WN / 16;
    const int w = tid >> 5;
    const int wy = w / WGX, wx = w % WGX;

    wmma::fragment<wmma::accumulator, 16, 16, 16, float> acc[MI][NI];
#pragma unroll
    for (int i = 0; i < MI; ++i)
#pragma unroll
        for (int j = 0; j < NI; ++j) wmma::fill_fragment(acc[i][j], 0.0f);

#pragma unroll
    for (int s = 0; s < STAGES - 1; ++s) load_stage(s, s);

    for (int c = 0; c < nchunks; ++c) {
        const int cur = c % STAGES;
        if (c + STAGES - 1 < nchunks) {
            load_stage((c + STAGES - 1) % STAGES, c + STAGES - 1);
            asm volatile("cp.async.wait_group %0;\n" :: "n"(STAGES - 1));
        } else {
            asm volatile("cp.async.wait_group 0;\n");
        }
        __syncthreads();

        const __nv_bfloat16* sAhi = smem + cur * STG;
        const __nv_bfloat16* sAlo = sAhi + TA;
        const __nv_bfloat16* sWhi = sAlo + TA;
        const __nv_bfloat16* sWlo = sWhi + TW;

#pragma unroll
        for (int ks = 0; ks < BKT / 16; ++ks) {
            wmma::fragment<wmma::matrix_a, 16, 16, 16, __nv_bfloat16, wmma::row_major> ah[MI], al[MI];
            wmma::fragment<wmma::matrix_b, 16, 16, 16, __nv_bfloat16, wmma::col_major> bh[NI], bl[NI];
#pragma unroll
            for (int i = 0; i < MI; ++i) {
                wmma::load_matrix_sync(ah[i], sAhi + (wy * WM + 16 * i) * LDT + ks * 16, LDT);
                wmma::load_matrix_sync(al[i], sAlo + (wy * WM + 16 * i) * LDT + ks * 16, LDT);
            }
#pragma unroll
            for (int j = 0; j < NI; ++j) {
                wmma::load_matrix_sync(bh[j], sWhi + (wx * WN + 16 * j) * LDT + ks * 16, LDT);
                wmma::load_matrix_sync(bl[j], sWlo + (wx * WN + 16 * j) * LDT + ks * 16, LDT);
            }
#pragma unroll
            for (int i = 0; i < MI; ++i)
#pragma unroll
                for (int j = 0; j < NI; ++j) {
                    wmma::mma_sync(acc[i][j], ah[i], bh[j], acc[i][j]);
                    wmma::mma_sync(acc[i][j], ah[i], bl[j], acc[i][j]);
                    wmma::mma_sync(acc[i][j], al[i], bh[j], acc[i][j]);
                }
        }
        __syncthreads();
    }

    // Epilogue: stage accumulators in smem, then coalesced global writes.
    constexpr int LDCc = BNp + 4;
    float* stage = reinterpret_cast<float*>(smem);
#pragma unroll
    for (int i = 0; i < MI; ++i)
#pragma unroll
        for (int j = 0; j < NI; ++j)
            wmma::store_matrix_sync(stage + (wy * WM + 16 * i) * LDCc + wx * WN + 16 * j,
                                    acc[i][j], LDCc, wmma::mem_row_major);
    __syncthreads();

#pragma unroll
    for (int i = 0; i < BMp * BNp / 4 / THREADS; ++i) {
        int f = tid + i * THREADS;
        int row = f / (BNp / 4);
        int c4  = (f % (BNp / 4)) * 4;
        float4 v4 = *reinterpret_cast<float4*>(&stage[row * LDCc + c4]);
        float v[4] = {v4.x, v4.y, v4.z, v4.w};
#pragma unroll
        for (int q = 0; q < 4; ++q) {
            if (EPI >= 2) v[q] += bias[n0 + c4 + q];
            v[q] = fmaxf(v[q], 0.0f);
        }
        long gm = m0 + row;
        if (EPI == 0) {
            *reinterpret_cast<float4*>((float*)Cout + gm * N + n0 + c4) =
                make_float4(v[0], v[1], v[2], v[3]);
        } else {
            __nv_bfloat16* cp = (__nv_bfloat16*)Cout + gm * (2L * N);
            __nv_bfloat16 h[4]; float lo[4];
#pragma unroll
            for (int q = 0; q < 4; ++q) {
                h[q]  = __float2bfloat16(v[q]);
                lo[q] = v[q] - __bfloat162float(h[q]);
            }
            __nv_bfloat162 hh0; hh0.x = h[0]; hh0.y = h[1];
            __nv_bfloat162 hh1; hh1.x = h[2]; hh1.y = h[3];
            reinterpret_cast<__nv_bfloat162*>(cp + n0 + c4)[0] = hh0;
            reinterpret_cast<__nv_bfloat162*>(cp + n0 + c4)[1] = hh1;
            __nv_bfloat162 ll0; ll0.x = __float2bfloat16(lo[0]); ll0.y = __float2bfloat16(lo[1]);
            __nv_bfloat162 ll1; ll1.x = __float2bfloat16(lo[2]); ll1.y = __float2bfloat16(lo[3]);
            reinterpret_cast<__nv_bfloat162*>(cp + N + n0 + c4)[0] = ll0;
            reinterpret_cast<__nv_bfloat162*>(cp + N + n0 + c4)[1] = ll1;
            if (EPI == 3) {
                *reinterpret_cast<float4*>(Cdual + gm * N + n0 + c4) =
                    make_float4(v[0], v[1], v[2], v[3]);
            }
        }
    }
}

// ---------------------------------------------------------------------------
// LSTM gates + reward + hs concat, fused. One block per batch row.
// ---------------------------------------------------------------------------
__global__ __launch_bounds__(256)
void gates_kernel(const float* __restrict__ cc, float* __restrict__ cell,
                  const float* __restrict__ rW, const float* __restrict__ rb,
                  const float* __restrict__ acts, const float* __restrict__ latent,
                  int t, float* __restrict__ preds, float* __restrict__ rewards,
                  __nv_bfloat16* __restrict__ hs)
{
    const int b = blockIdx.x, tid = threadIdx.x;
    const float* ccb = cc + (long)b * S4;
    float* cb  = cell + (long)b * SS;
    float* pr  = preds + ((long)t * BB + b) * SS;
    __nv_bfloat16* hsb = hs + (long)b * (2 * KFC);

    float rsum = 0.f;
#pragma unroll
    for (int i = 0; i < 8; ++i) {
        int s = tid + i * 256;
        float ci = ccb[s];
        float cf = ccb[SS + s];
        float co = ccb[2 * SS + s];
        float cg = ccb[3 * SS + s];
        float ig = 1.f / (1.f + expf(-ci));
        float fg = 1.f / (1.f + expf(-cf));
        float og = 1.f / (1.f + expf(-co));
        float gg = tanhf(cg);
        float cn = fg * cb[s] + ig * gg;
        cb[s] = cn;
        float h = og * tanhf(cn);
        pr[s] = h;
        split_write(&hsb[s], &hsb[KFC + s], h);
        rsum += h * rW[s];
    }

    __shared__ float red[256];
    red[tid] = rsum;
    __syncthreads();
    for (int s2 = 128; s2 > 0; s2 >>= 1) {
        if (tid < s2) red[tid] += red[tid + s2];
        __syncthreads();
    }
    if (tid == 0) rewards[(long)t * BB + b] = red[0] + rb[0];

    if (tid < AA) {
        float v = acts[(long)b * (TT * AA) + t * AA + tid];
        split_write(&hsb[SS + tid], &hsb[KFC + SS + tid], v);
    } else if (tid < AA + PP) {
        int j = tid - AA;
        float v = latent[(long)b * PP + j];
        split_write(&hsb[SS + AA + j], &hsb[KFC + SS + AA + j], v);
    }
}

// ---------------------------------------------------------------------------
// Launch
// ---------------------------------------------------------------------------
// Small config: 64x64 tile, 4 warps (32x32 each), 3 stages.
#define SMEM_S (3 * (4 * 64 * LDT) * (int)sizeof(__nv_bfloat16))   // 110592 B
// Big config: 128x128 tile, 8 warps (64x32 each), 2 stages.
#define SMEM_B (2 * (4 * 128 * LDT) * (int)sizeof(__nv_bfloat16))  // 147456 B

extern "C" void kernel_launch(void* const* d_in, const int* /*in_sizes*/, int /*n_in*/,
                              void* d_out, int /*out_size*/) {
    const float* state  = (const float*)d_in[0];
    const float* acts   = (const float*)d_in[1];
    const float* latent = (const float*)d_in[2];
    const float* fcW    = (const float*)d_in[3];
    const float* fcb    = (const float*)d_in[4];
    const float* fc1W   = (const float*)d_in[5];
    const float* fc2W   = (const float*)d_in[6];
    const float* WW     = (const float*)d_in[7];
    const float* rW     = (const float*)d_in[8];
    const float* rb     = (const float*)d_in[9];

    float* preds   = (float*)d_out;
    float* rewards = preds + (long)TT * BB * SS;

    __nv_bfloat16 *fc1e, *fc2b, *WWb, *fcWb, *hb, *x1b, *x2b, *hsb;
    float *cc, *cell;
    cudaGetSymbolAddress((void**)&fc1e, g_fc1e);
    cudaGetSymbolAddress((void**)&fc2b, g_fc2b);
    cudaGetSymbolAddress((void**)&WWb,  g_WWb);
    cudaGetSymbolAddress((void**)&fcWb, g_fcWb);
    cudaGetSymbolAddress((void**)&hb,   g_hb);
    cudaGetSymbolAddress((void**)&x1b,  g_x1b);
    cudaGetSymbolAddress((void**)&x2b,  g_x2b);
    cudaGetSymbolAddress((void**)&hsb,  g_hsb);
    cudaGetSymbolAddress((void**)&cc,   g_cc);
    cudaGetSymbolAddress((void**)&cell, g_cell);

    // Opt in to >48KB dynamic smem (idempotent; immediate host-side call).
    cudaFuncSetAttribute((const void*)gemm3<64,64,32,32,128,3,0>, cudaFuncAttributeMaxDynamicSharedMemorySize, SMEM_S);
    cudaFuncSetAttribute((const void*)gemm3<64,64,32,32,128,3,1>, cudaFuncAttributeMaxDynamicSharedMemorySize, SMEM_S);
    cudaFuncSetAttribute((const void*)gemm3<64,64,32,32,128,3,2>, cudaFuncAttributeMaxDynamicSharedMemorySize, SMEM_S);
    cudaFuncSetAttribute((const void*)gemm3<64,64,32,32,128,3,3>, cudaFuncAttributeMaxDynamicSharedMemorySize, SMEM_S);
    cudaFuncSetAttribute((const void*)gemm3<128,128,64,32,256,2,0>, cudaFuncAttributeMaxDynamicSharedMemorySize, SMEM_B);

    // Weight packing (runs on every replay; ~1% of total time)
    pack_fc1eff<<<(unsigned)(((long)SS * SS) / 256), 256>>>(fc1W, fc1e);
    pack_weight<<<(unsigned)(((long)SS * SS) / 256), 256>>>(fc2W, fc2b, SS,  (long)SS * SS);
    pack_weight<<<(unsigned)(((long)S4 * SS) / 256), 256>>>(WW,   WWb,  SS,  (long)S4 * SS);
    pack_weight<<<(unsigned)(((long)SS * KFC) / 256), 256>>>(fcW, fcWb, KFC, (long)SS * KFC);
    build_hs0<<<(unsigned)(((long)BB * KFC) / 256), 256>>>(state, acts, latent, hsb);

    dim3 g2048(SS / 64, BB / 64);     // (32, 4) small config
    dim3 g8192(S4 / 128, BB / 128);   // (64, 2) big config

    // hidden = cell = relu(fc(hs0)): one GEMM, dual store
    gemm3<64,64,32,32,128,3,3><<<g2048, 128, SMEM_S>>>(hsb, fcWb, fcb, hb, cell, SS, KFC);

    for (int t = 0; t < TT; ++t) {
        gemm3<64,64,32,32,128,3,1><<<g2048, 128, SMEM_S>>>(hb,  fc1e, nullptr, x1b, nullptr, SS, SS);
        gemm3<64,64,32,32,128,3,1><<<g2048, 128, SMEM_S>>>(x1b, fc2b, nullptr, x2b, nullptr, SS, SS);
        gemm3<128,128,64,32,256,2,0><<<g8192, 256, SMEM_B>>>(x2b, WWb, nullptr, cc, nullptr, S4, SS);
        gates_kernel<<<BB, 256>>>(cc, cell, rW, rb, acts, latent, t, preds, rewards, hsb);
        if (t + 1 < TT)
            gemm3<64,64,32,32,128,3,2><<<g2048, 128, SMEM_S>>>(hsb, fcWb, fcb, hb, nullptr, SS, KFC);
    }
}